// round 2
// baseline (speedup 1.0000x reference)
#include <cuda_runtime.h>
#include <cuda_bf16.h>
#include <math.h>

// Problem constants
#define BB 2
#define SS 2048
#define DD 1024
#define HH 16
#define DK 64
#define ND (2*SS-1)          // 4095 relative-distance slots
#define MM (BB*SS)           // 4096 rows in the GEMMs

// Scratch (allocation-free: __device__ globals)
__device__ float g_q[BB*HH*SS*DK];     // [B,H,S,DK]
__device__ float g_k[BB*HH*SS*DK];
__device__ float g_v[BB*HH*SS*DK];
__device__ float g_ctx[BB*SS*HH*DK];   // [B,S,H*DK]
__device__ float g_bias[HH*ND];        // [H, rel+S-1]

// ---------------------------------------------------------------------------
// Bias precompute: bucket(rel) -> rel_bias[bucket][h], laid out per-head by
// relative distance so the attention kernel does a 127-float smem load/tile.
// Double-precision log to match jnp float math + int32 truncation robustly.
// ---------------------------------------------------------------------------
__global__ void bias_precompute(const float* __restrict__ rel_bias) {
    int idx = blockIdx.x * blockDim.x + threadIdx.x;
    if (idx >= ND) return;
    int rel = idx - (SS - 1);        // rel = mem - ctx = j - i
    int n = -rel;
    int ret = (n < 0) ? 16 : 0;      // num_buckets//2 = 16
    n = (n < 0) ? -n : n;
    int bucket;
    if (n < 8) {                     // max_exact = 8
        bucket = n;
    } else {
        double v = log((double)n / 8.0) / log(16.0) * 8.0;
        int vi = 8 + (int)v;
        bucket = (vi < 15) ? vi : 15;
    }
    bucket += ret;
#pragma unroll
    for (int h = 0; h < HH; h++)
        g_bias[h * ND + idx] = rel_bias[bucket * HH + h];
}

// ---------------------------------------------------------------------------
// SGEMM (NT): C[m,n] = sum_k A[m,k] * B[n,k].  M=4096, N=1024, K=1024.
// 128x128 tile, BK=8, 256 threads, 8x8 per-thread register blocking.
// MODE 0: C is plain [M, N] row-major (output projection -> d_out)
// MODE 1: C written as [B, H, S, DK] (fused head-split for q/k/v)
// ---------------------------------------------------------------------------
template <int MODE>
__global__ __launch_bounds__(256) void sgemm_nt(const float* __restrict__ A,
                                                const float* __restrict__ Bm,
                                                float* __restrict__ C) {
    __shared__ float As[8][128];
    __shared__ float Bs[8][128];
    const int K = 1024;
    const int bm = blockIdx.y * 128;
    const int bn = blockIdx.x * 128;
    const int t  = threadIdx.x;
    const int tx = t & 15, ty = t >> 4;
    const int m0 = ty * 8, n0 = tx * 8;

    const int lrow = t >> 1;          // 0..127
    const int lc4  = (t & 1) * 4;     // 0 or 4

    float acc[8][8];
#pragma unroll
    for (int i = 0; i < 8; i++)
#pragma unroll
        for (int j = 0; j < 8; j++) acc[i][j] = 0.f;

    const float* aptr = A  + (size_t)(bm + lrow) * K + lc4;
    const float* bptr = Bm + (size_t)(bn + lrow) * K + lc4;

    for (int k0 = 0; k0 < K; k0 += 8) {
        float4 av = *(const float4*)(aptr + k0);
        float4 bv = *(const float4*)(bptr + k0);
        __syncthreads();
        As[lc4 + 0][lrow] = av.x; As[lc4 + 1][lrow] = av.y;
        As[lc4 + 2][lrow] = av.z; As[lc4 + 3][lrow] = av.w;
        Bs[lc4 + 0][lrow] = bv.x; Bs[lc4 + 1][lrow] = bv.y;
        Bs[lc4 + 2][lrow] = bv.z; Bs[lc4 + 3][lrow] = bv.w;
        __syncthreads();
#pragma unroll
        for (int kk = 0; kk < 8; kk++) {
            float a[8], b[8];
            *(float4*)(a)     = *(const float4*)&As[kk][m0];
            *(float4*)(a + 4) = *(const float4*)&As[kk][m0 + 4];
            *(float4*)(b)     = *(const float4*)&Bs[kk][n0];
            *(float4*)(b + 4) = *(const float4*)&Bs[kk][n0 + 4];
#pragma unroll
            for (int i = 0; i < 8; i++)
#pragma unroll
                for (int j = 0; j < 8; j++)
                    acc[i][j] = fmaf(a[i], b[j], acc[i][j]);
        }
    }

    // Epilogue
#pragma unroll
    for (int i = 0; i < 8; i++) {
        const int m = bm + m0 + i;
#pragma unroll
        for (int j4 = 0; j4 < 8; j4 += 4) {
            const int n = bn + n0 + j4;
            float4 v = make_float4(acc[i][j4], acc[i][j4+1], acc[i][j4+2], acc[i][j4+3]);
            if (MODE == 0) {
                *(float4*)&C[(size_t)m * 1024 + n] = v;
            } else {
                const int b = m >> 11, s = m & 2047;       // m = b*S + s
                const int h = n >> 6,  dk = n & 63;        // n = h*DK + dk (dk%4==0, stays in head)
                *(float4*)&C[(((size_t)(b * HH + h) * SS) + s) * DK + dk] = v;
            }
        }
    }
}

// ---------------------------------------------------------------------------
// Flash attention (fp32): one CTA = (b,h) x 64 query rows. Online softmax.
// smem: Qs/Ks/Vs/Ps each [64][68] + 128-float bias diagonal slice (~70 KB).
// ---------------------------------------------------------------------------
__global__ __launch_bounds__(256) void attn_kernel() {
    extern __shared__ float sm[];
    float* Qs = sm;                  // [64][68]
    float* Ks = Qs + 64 * 68;
    float* Vs = Ks + 64 * 68;
    float* Ps = Vs + 64 * 68;
    float* bias_s = Ps + 64 * 68;    // [128] (127 used)

    const int bh = blockIdx.y;       // b*H + h
    const int h  = bh & (HH - 1);
    const int b  = bh >> 4;
    const int qbase = blockIdx.x * 64;
    const int t  = threadIdx.x;
    const int tx = t & 15, ty = t >> 4;
    const int m0 = ty * 4, n0 = tx * 4;

    const float* qptr = g_q + (size_t)bh * SS * DK;
    const float* kptr = g_k + (size_t)bh * SS * DK;
    const float* vptr = g_v + (size_t)bh * SS * DK;

    // Load Q tile [64, 64]
    for (int i = t; i < 64 * 16; i += 256) {
        const int row = i >> 4, c4 = (i & 15) * 4;
        *(float4*)&Qs[row * 68 + c4] = *(const float4*)&qptr[(size_t)(qbase + row) * DK + c4];
    }

    float m_i[4], l_i[4], acc[4][4];
#pragma unroll
    for (int i = 0; i < 4; i++) {
        m_i[i] = -INFINITY; l_i[i] = 0.f;
#pragma unroll
        for (int j = 0; j < 4; j++) acc[i][j] = 0.f;
    }

    for (int kt = 0; kt < SS / 64; kt++) {
        const int kbase = kt * 64;
        __syncthreads();   // previous iteration's Ks/Vs/Ps fully consumed
        for (int i = t; i < 64 * 16; i += 256) {
            const int row = i >> 4, c4 = (i & 15) * 4;
            *(float4*)&Ks[row * 68 + c4] = *(const float4*)&kptr[(size_t)(kbase + row) * DK + c4];
            *(float4*)&Vs[row * 68 + c4] = *(const float4*)&vptr[(size_t)(kbase + row) * DK + c4];
        }
        if (t < 127) {
            int off = (kbase - qbase) + (t - 63) + (SS - 1);
            off = max(0, min(ND - 1, off));
            bias_s[t] = g_bias[h * ND + off];
        }
        __syncthreads();

        // s[i][j] = Q[m0+i] . K[n0+j]
        float s[4][4];
#pragma unroll
        for (int i = 0; i < 4; i++)
#pragma unroll
            for (int j = 0; j < 4; j++) s[i][j] = 0.f;

#pragma unroll 4
        for (int d = 0; d < 64; d += 4) {
            float4 aa[4], bb[4];
#pragma unroll
            for (int i = 0; i < 4; i++) aa[i] = *(const float4*)&Qs[(m0 + i) * 68 + d];
#pragma unroll
            for (int j = 0; j < 4; j++) bb[j] = *(const float4*)&Ks[(n0 + j) * 68 + d];
#pragma unroll
            for (int i = 0; i < 4; i++)
#pragma unroll
                for (int j = 0; j < 4; j++) {
                    s[i][j] = fmaf(aa[i].x, bb[j].x, s[i][j]);
                    s[i][j] = fmaf(aa[i].y, bb[j].y, s[i][j]);
                    s[i][j] = fmaf(aa[i].z, bb[j].z, s[i][j]);
                    s[i][j] = fmaf(aa[i].w, bb[j].w, s[i][j]);
                }
        }

        // bias + online softmax update
#pragma unroll
        for (int i = 0; i < 4; i++) {
#pragma unroll
            for (int j = 0; j < 4; j++)
                s[i][j] += bias_s[(n0 + j) - (m0 + i) + 63];

            float rmax = fmaxf(fmaxf(s[i][0], s[i][1]), fmaxf(s[i][2], s[i][3]));
#pragma unroll
            for (int o = 8; o > 0; o >>= 1)
                rmax = fmaxf(rmax, __shfl_xor_sync(0xffffffffu, rmax, o));
            const float m_new = fmaxf(m_i[i], rmax);
            const float scale = __expf(m_i[i] - m_new);   // exp(-inf)=0 on first tile
            float rsum = 0.f;
#pragma unroll
            for (int j = 0; j < 4; j++) {
                s[i][j] = __expf(s[i][j] - m_new);
                rsum += s[i][j];
            }
#pragma unroll
            for (int o = 8; o > 0; o >>= 1)
                rsum += __shfl_xor_sync(0xffffffffu, rsum, o);
            l_i[i] = l_i[i] * scale + rsum;
            m_i[i] = m_new;
#pragma unroll
            for (int j = 0; j < 4; j++) acc[i][j] *= scale;
            *(float4*)&Ps[(m0 + i) * 68 + n0] = make_float4(s[i][0], s[i][1], s[i][2], s[i][3]);
        }
        __syncthreads();

        // acc += P @ V  (P [64 x 64k], V [64k x 64d])
#pragma unroll 4
        for (int kk = 0; kk < 64; kk += 4) {
            float4 av[4];
#pragma unroll
            for (int i = 0; i < 4; i++) av[i] = *(const float4*)&Ps[(m0 + i) * 68 + kk];
            float4 bv0 = *(const float4*)&Vs[(kk + 0) * 68 + n0];
            float4 bv1 = *(const float4*)&Vs[(kk + 1) * 68 + n0];
            float4 bv2 = *(const float4*)&Vs[(kk + 2) * 68 + n0];
            float4 bv3 = *(const float4*)&Vs[(kk + 3) * 68 + n0];
#pragma unroll
            for (int i = 0; i < 4; i++) {
                acc[i][0] = fmaf(av[i].x, bv0.x, acc[i][0]);
                acc[i][1] = fmaf(av[i].x, bv0.y, acc[i][1]);
                acc[i][2] = fmaf(av[i].x, bv0.z, acc[i][2]);
                acc[i][3] = fmaf(av[i].x, bv0.w, acc[i][3]);
                acc[i][0] = fmaf(av[i].y, bv1.x, acc[i][0]);
                acc[i][1] = fmaf(av[i].y, bv1.y, acc[i][1]);
                acc[i][2] = fmaf(av[i].y, bv1.z, acc[i][2]);
                acc[i][3] = fmaf(av[i].y, bv1.w, acc[i][3]);
                acc[i][0] = fmaf(av[i].z, bv2.x, acc[i][0]);
                acc[i][1] = fmaf(av[i].z, bv2.y, acc[i][1]);
                acc[i][2] = fmaf(av[i].z, bv2.z, acc[i][2]);
                acc[i][3] = fmaf(av[i].z, bv2.w, acc[i][3]);
                acc[i][0] = fmaf(av[i].w, bv3.x, acc[i][0]);
                acc[i][1] = fmaf(av[i].w, bv3.y, acc[i][1]);
                acc[i][2] = fmaf(av[i].w, bv3.z, acc[i][2]);
                acc[i][3] = fmaf(av[i].w, bv3.w, acc[i][3]);
            }
        }
    }

    // Normalize + write ctx in [B, S, H*DK] layout for the output GEMM
#pragma unroll
    for (int i = 0; i < 4; i++) {
        const float inv = 1.0f / l_i[i];
        const int qrow = qbase + m0 + i;
        float4 v = make_float4(acc[i][0] * inv, acc[i][1] * inv,
                               acc[i][2] * inv, acc[i][3] * inv);
        *(float4*)&g_ctx[((size_t)(b * SS + qrow)) * DD + h * DK + n0] = v;
    }
}

// ---------------------------------------------------------------------------
extern "C" void kernel_launch(void* const* d_in, const int* in_sizes, int n_in,
                              void* d_out, int out_size) {
    const float* x        = (const float*)d_in[0];
    const float* q_w      = (const float*)d_in[1];
    const float* k_w      = (const float*)d_in[2];
    const float* v_w      = (const float*)d_in[3];
    const float* o_w      = (const float*)d_in[4];
    const float* rel_bias = (const float*)d_in[5];

    float *qp, *kp, *vp, *cp;
    cudaGetSymbolAddress((void**)&qp, g_q);
    cudaGetSymbolAddress((void**)&kp, g_k);
    cudaGetSymbolAddress((void**)&vp, g_v);
    cudaGetSymbolAddress((void**)&cp, g_ctx);

    bias_precompute<<<(ND + 255) / 256, 256>>>(rel_bias);

    dim3 gg(1024 / 128, MM / 128);   // (8, 32)
    sgemm_nt<1><<<gg, 256>>>(x, q_w, qp);
    sgemm_nt<1><<<gg, 256>>>(x, k_w, kp);
    sgemm_nt<1><<<gg, 256>>>(x, v_w, vp);

    const size_t smem = (4 * 64 * 68 + 128) * sizeof(float);
    cudaFuncSetAttribute(attn_kernel, cudaFuncAttributeMaxDynamicSharedMemorySize, (int)smem);
    attn_kernel<<<dim3(SS / 64, BB * HH), 256, smem>>>();

    sgemm_nt<0><<<gg, 256>>>(cp, o_w, (float*)d_out);
}

// round 7
// speedup vs baseline: 3.9937x; 3.9937x over previous
#include <cuda_runtime.h>
#include <cuda_bf16.h>
#include <math.h>

// Problem constants
#define BB 2
#define SS 2048
#define DD 1024
#define HH 16
#define DK 64
#define ND (2*SS-1)          // 4095 relative-distance slots
#define MM (BB*SS)           // 4096 rows in the GEMMs

// Scratch (allocation-free: __device__ globals)
__device__ float g_q[BB*HH*SS*DK];     // [B,H,S,DK]
__device__ float g_k[BB*HH*SS*DK];
__device__ float g_v[BB*HH*SS*DK];
__device__ float g_ctx[BB*SS*HH*DK];   // [B,S,H*DK]
__device__ float g_bias[HH*ND];        // [H, rel+S-1]

// ---------------------------------------------------------------------------
// TF32 helpers
// ---------------------------------------------------------------------------
__device__ __forceinline__ unsigned f2tf(float x) {
    unsigned u;
    asm("cvt.rna.tf32.f32 %0, %1;" : "=r"(u) : "f"(x));
    return u;
}

__device__ __forceinline__ void mma8(float& d0, float& d1, float& d2, float& d3,
                                     unsigned a0, unsigned a1, unsigned a2, unsigned a3,
                                     unsigned b0, unsigned b1) {
    asm volatile("mma.sync.aligned.m16n8k8.row.col.f32.tf32.tf32.f32 "
                 "{%0,%1,%2,%3},{%4,%5,%6,%7},{%8,%9},{%0,%1,%2,%3};"
                 : "+f"(d0), "+f"(d1), "+f"(d2), "+f"(d3)
                 : "r"(a0), "r"(a1), "r"(a2), "r"(a3), "r"(b0), "r"(b1));
}

// ---------------------------------------------------------------------------
// Bias precompute (unchanged, correctness-proven)
// ---------------------------------------------------------------------------
__global__ void bias_precompute(const float* __restrict__ rel_bias) {
    int idx = blockIdx.x * blockDim.x + threadIdx.x;
    if (idx >= ND) return;
    int rel = idx - (SS - 1);        // rel = mem - ctx = j - i
    int n = -rel;
    int ret = (n < 0) ? 16 : 0;      // num_buckets//2 = 16
    n = (n < 0) ? -n : n;
    int bucket;
    if (n < 8) {
        bucket = n;
    } else {
        double v = log((double)n / 8.0) / log(16.0) * 8.0;
        int vi = 8 + (int)v;
        bucket = (vi < 15) ? vi : 15;
    }
    bucket += ret;
#pragma unroll
    for (int h = 0; h < HH; h++)
        g_bias[h * ND + idx] = rel_bias[bucket * HH + h];
}

// ---------------------------------------------------------------------------
// TF32 tensor-core GEMM (NT): C[m,n] = sum_k A[m,k] * B[n,k].
// M=4096, N=1024, K=1024. 128x128x32 tile, 256 threads (8 warps, 2x4 grid),
// each warp 64x32 via m16n8k8 tiles. All fragment LDS bank-conflict-free.
// MODE 0: C row-major [M,N]; MODE 1: C as [B,H,S,DK] (fused head split).
// ---------------------------------------------------------------------------
template <int MODE>
__global__ __launch_bounds__(256) void gemm_tf32(const float* __restrict__ A,
                                                 const float* __restrict__ Bm,
                                                 float* __restrict__ C) {
    __shared__ unsigned As[128][36];   // stride 36 mod 32 = 4 -> banks 4g+tig
    __shared__ unsigned Bs[128][36];
    const int t = threadIdx.x, lane = t & 31, g = lane >> 2, tig = lane & 3;
    const int w = t >> 5, wm = w >> 2, wn = w & 3;
    const int bm = blockIdx.y * 128, bn = blockIdx.x * 128;

    float acc[4][4][4];
#pragma unroll
    for (int a = 0; a < 4; a++)
#pragma unroll
        for (int b = 0; b < 4; b++)
#pragma unroll
            for (int c = 0; c < 4; c++) acc[a][b][c] = 0.f;

    for (int k0 = 0; k0 < 1024; k0 += 32) {
        __syncthreads();
#pragma unroll
        for (int i = 0; i < 4; i++) {
            int lin = t + 256 * i;             // 0..1023 float4-chunks
            int r = lin >> 3, c4 = (lin & 7) * 4;
            float4 av = *(const float4*)(A  + (size_t)(bm + r) * 1024 + k0 + c4);
            float4 bv = *(const float4*)(Bm + (size_t)(bn + r) * 1024 + k0 + c4);
            *(uint4*)&As[r][c4] = make_uint4(f2tf(av.x), f2tf(av.y), f2tf(av.z), f2tf(av.w));
            *(uint4*)&Bs[r][c4] = make_uint4(f2tf(bv.x), f2tf(bv.y), f2tf(bv.z), f2tf(bv.w));
        }
        __syncthreads();
#pragma unroll
        for (int kk = 0; kk < 32; kk += 8) {
            unsigned af[4][4], bf[4][2];
#pragma unroll
            for (int tm = 0; tm < 4; tm++) {
                int r = wm * 64 + tm * 16 + g;
                af[tm][0] = As[r][kk + tig];
                af[tm][1] = As[r + 8][kk + tig];
                af[tm][2] = As[r][kk + tig + 4];
                af[tm][3] = As[r + 8][kk + tig + 4];
            }
#pragma unroll
            for (int tn = 0; tn < 4; tn++) {
                int c = wn * 32 + tn * 8 + g;
                bf[tn][0] = Bs[c][kk + tig];
                bf[tn][1] = Bs[c][kk + tig + 4];
            }
#pragma unroll
            for (int tm = 0; tm < 4; tm++)
#pragma unroll
                for (int tn = 0; tn < 4; tn++)
                    mma8(acc[tm][tn][0], acc[tm][tn][1], acc[tm][tn][2], acc[tm][tn][3],
                         af[tm][0], af[tm][1], af[tm][2], af[tm][3],
                         bf[tn][0], bf[tn][1]);
        }
    }

#pragma unroll
    for (int tm = 0; tm < 4; tm++) {
#pragma unroll
        for (int tn = 0; tn < 4; tn++) {
            int m = bm + wm * 64 + tm * 16 + g;
            int n = bn + wn * 32 + tn * 8 + tig * 2;
            float2 v0 = make_float2(acc[tm][tn][0], acc[tm][tn][1]);
            float2 v1 = make_float2(acc[tm][tn][2], acc[tm][tn][3]);
            if (MODE == 0) {
                *(float2*)&C[(size_t)m * 1024 + n] = v0;
                *(float2*)&C[(size_t)(m + 8) * 1024 + n] = v1;
            } else {
                int h = n >> 6, dk = n & 63;
                int b0_ = m >> 11, s0 = m & 2047;
                *(float2*)&C[(((size_t)(b0_ * HH + h)) * SS + s0) * DK + dk] = v0;
                int m1 = m + 8;
                int b1_ = m1 >> 11, s1 = m1 & 2047;
                *(float2*)&C[(((size_t)(b1_ * HH + h)) * SS + s1) * DK + dk] = v1;
            }
        }
    }
}

// ---------------------------------------------------------------------------
// Flash attention with TF32 mma. CTA = 128 q-rows x (b,h); k in 64-col tiles.
// 8 warps; warp w owns q-rows [16w, 16w+16) and the FULL 64-col width, so the
// online softmax is entirely warp-local (shfl over the lane quad).
// P roundtrips through per-warp-private smem to fix the C->A layout mismatch.
// ---------------------------------------------------------------------------
__global__ __launch_bounds__(256) void attn_tf32() {
    extern __shared__ unsigned smu[];
    unsigned* Qs = smu;                   // [128][68]  stride 68 (mod32=4)
    unsigned* Ps = Qs + 128 * 68;         // [64][140]  stride 140 (mod32=12)
    unsigned* Ks = Ps + 64 * 140;         // [64][72]   stride 72 (mod32=8)
    unsigned* Vs = Ks + 64 * 72;          // [64][72]
    float* bias_s = (float*)(Vs + 64 * 72);   // [192] (191 used)

    const int t = threadIdx.x, lane = t & 31, g = lane >> 2, tig = lane & 3;
    const int w = t >> 5;
    const int bh = blockIdx.y, h = bh & 15, b_ = bh >> 4;
    const int q0 = blockIdx.x * 128;
    const float* qg = g_q + (size_t)bh * SS * DK;
    const float* kg = g_k + (size_t)bh * SS * DK;
    const float* vg = g_v + (size_t)bh * SS * DK;

    // Stage Q [128][64] -> Qs (coalesced float4, cvt to tf32)
#pragma unroll
    for (int i = 0; i < 8; i++) {
        int lin = t + 256 * i;            // 0..2047
        int r = lin >> 4, c4 = (lin & 15) * 4;
        float4 v = *(const float4*)(qg + (size_t)(q0 + r) * DK + c4);
        *(uint4*)&Qs[r * 68 + c4] = make_uint4(f2tf(v.x), f2tf(v.y), f2tf(v.z), f2tf(v.w));
    }

    float oacc[8][4];
#pragma unroll
    for (int tn = 0; tn < 8; tn++)
#pragma unroll
        for (int c = 0; c < 4; c++) oacc[tn][c] = 0.f;
    float m0 = -INFINITY, m1 = -INFINITY, l0 = 0.f, l1 = 0.f;
    const int rb = w * 16;
    const int r0 = rb + g, r1 = rb + g + 8;

    for (int kt = 0; kt < SS / 64; kt++) {
        const int kb = kt * 64;
        __syncthreads();                  // prev Ks/Vs/Ps consumed
#pragma unroll
        for (int i = 0; i < 4; i++) {
            int lin = t + 256 * i;        // 0..1023
            int c = lin >> 4, d4 = (lin & 15) * 4;
            float4 kv = *(const float4*)(kg + (size_t)(kb + c) * DK + d4);
            float4 vv = *(const float4*)(vg + (size_t)(kb + c) * DK + d4);
            *(uint4*)&Ks[c * 72 + d4] = make_uint4(f2tf(kv.x), f2tf(kv.y), f2tf(kv.z), f2tf(kv.w));
            *(uint4*)&Vs[c * 72 + d4] = make_uint4(f2tf(vv.x), f2tf(vv.y), f2tf(vv.z), f2tf(vv.w));
        }
        if (t < 191)                      // rel in [-2047, 2047] exactly; no clamp needed
            bias_s[t] = g_bias[h * ND + (kb - q0 - 127 + t) + (SS - 1)];
        __syncthreads();

        // S = Q @ K^T  (warp strip: 16 rows x 64 cols)
        float sv[8][4];
#pragma unroll
        for (int tn = 0; tn < 8; tn++)
#pragma unroll
            for (int c = 0; c < 4; c++) sv[tn][c] = 0.f;

#pragma unroll
        for (int d0 = 0; d0 < 64; d0 += 8) {
            unsigned a0 = Qs[r0 * 68 + d0 + tig];
            unsigned a1 = Qs[r1 * 68 + d0 + tig];
            unsigned a2 = Qs[r0 * 68 + d0 + tig + 4];
            unsigned a3 = Qs[r1 * 68 + d0 + tig + 4];
#pragma unroll
            for (int tn = 0; tn < 8; tn++) {
                unsigned bf0 = Ks[(tn * 8 + g) * 72 + d0 + tig];
                unsigned bf1 = Ks[(tn * 8 + g) * 72 + d0 + tig + 4];
                mma8(sv[tn][0], sv[tn][1], sv[tn][2], sv[tn][3], a0, a1, a2, a3, bf0, bf1);
            }
        }

        // bias + warp-local online softmax (rows r0, r1)
        float mx0 = -INFINITY, mx1 = -INFINITY;
#pragma unroll
        for (int tn = 0; tn < 8; tn++) {
            int c = tn * 8 + tig * 2;
            sv[tn][0] += bias_s[c - r0 + 127];
            sv[tn][1] += bias_s[c + 1 - r0 + 127];
            sv[tn][2] += bias_s[c - r1 + 127];
            sv[tn][3] += bias_s[c + 1 - r1 + 127];
            mx0 = fmaxf(mx0, fmaxf(sv[tn][0], sv[tn][1]));
            mx1 = fmaxf(mx1, fmaxf(sv[tn][2], sv[tn][3]));
        }
        mx0 = fmaxf(mx0, __shfl_xor_sync(0xffffffffu, mx0, 1));
        mx0 = fmaxf(mx0, __shfl_xor_sync(0xffffffffu, mx0, 2));
        mx1 = fmaxf(mx1, __shfl_xor_sync(0xffffffffu, mx1, 1));
        mx1 = fmaxf(mx1, __shfl_xor_sync(0xffffffffu, mx1, 2));
        const float mn0 = fmaxf(m0, mx0), mn1 = fmaxf(m1, mx1);
        const float sc0 = __expf(m0 - mn0), sc1 = __expf(m1 - mn1);
        float s0 = 0.f, s1 = 0.f;
#pragma unroll
        for (int tn = 0; tn < 8; tn++) {
            sv[tn][0] = __expf(sv[tn][0] - mn0);
            sv[tn][1] = __expf(sv[tn][1] - mn0);
            sv[tn][2] = __expf(sv[tn][2] - mn1);
            sv[tn][3] = __expf(sv[tn][3] - mn1);
            s0 += sv[tn][0] + sv[tn][1];
            s1 += sv[tn][2] + sv[tn][3];
        }
        s0 += __shfl_xor_sync(0xffffffffu, s0, 1);
        s0 += __shfl_xor_sync(0xffffffffu, s0, 2);
        s1 += __shfl_xor_sync(0xffffffffu, s1, 1);
        s1 += __shfl_xor_sync(0xffffffffu, s1, 2);
        l0 = l0 * sc0 + s0; l1 = l1 * sc1 + s1;
        m0 = mn0; m1 = mn1;

        // rescale O, spill P (warp-private rows -> only __syncwarp needed)
#pragma unroll
        for (int tn = 0; tn < 8; tn++) {
            oacc[tn][0] *= sc0; oacc[tn][1] *= sc0;
            oacc[tn][2] *= sc1; oacc[tn][3] *= sc1;
            int c = tn * 8 + tig * 2;
            Ps[(c)     * 140 + r0] = f2tf(sv[tn][0]);
            Ps[(c + 1) * 140 + r0] = f2tf(sv[tn][1]);
            Ps[(c)     * 140 + r1] = f2tf(sv[tn][2]);
            Ps[(c + 1) * 140 + r1] = f2tf(sv[tn][3]);
        }
        __syncwarp();

        // O += P @ V
#pragma unroll
        for (int c0 = 0; c0 < 64; c0 += 8) {
            unsigned a0 = Ps[(c0 + tig) * 140 + r0];
            unsigned a1 = Ps[(c0 + tig) * 140 + r1];
            unsigned a2 = Ps[(c0 + tig + 4) * 140 + r0];
            unsigned a3 = Ps[(c0 + tig + 4) * 140 + r1];
#pragma unroll
            for (int tn = 0; tn < 8; tn++) {
                unsigned bf0 = Vs[(c0 + tig) * 72 + tn * 8 + g];
                unsigned bf1 = Vs[(c0 + tig + 4) * 72 + tn * 8 + g];
                mma8(oacc[tn][0], oacc[tn][1], oacc[tn][2], oacc[tn][3],
                     a0, a1, a2, a3, bf0, bf1);
            }
        }
    }

    // Normalize + write ctx in [B, S, H*DK]
    const float i0 = 1.f / l0, i1 = 1.f / l1;
    float* op = g_ctx + ((size_t)b_ * SS + q0) * DD + h * DK;
#pragma unroll
    for (int tn = 0; tn < 8; tn++) {
        int n = tn * 8 + tig * 2;
        *(float2*)&op[(size_t)(rb + g) * DD + n] =
            make_float2(oacc[tn][0] * i0, oacc[tn][1] * i0);
        *(float2*)&op[(size_t)(rb + g + 8) * DD + n] =
            make_float2(oacc[tn][2] * i1, oacc[tn][3] * i1);
    }
}

// ---------------------------------------------------------------------------
extern "C" void kernel_launch(void* const* d_in, const int* in_sizes, int n_in,
                              void* d_out, int out_size) {
    const float* x        = (const float*)d_in[0];
    const float* q_w      = (const float*)d_in[1];
    const float* k_w      = (const float*)d_in[2];
    const float* v_w      = (const float*)d_in[3];
    const float* o_w      = (const float*)d_in[4];
    const float* rel_bias = (const float*)d_in[5];

    float *qp, *kp, *vp, *cp;
    cudaGetSymbolAddress((void**)&qp, g_q);
    cudaGetSymbolAddress((void**)&kp, g_k);
    cudaGetSymbolAddress((void**)&vp, g_v);
    cudaGetSymbolAddress((void**)&cp, g_ctx);

    bias_precompute<<<(ND + 255) / 256, 256>>>(rel_bias);

    dim3 gg(1024 / 128, MM / 128);   // (8, 32)
    gemm_tf32<1><<<gg, 256>>>(x, q_w, qp);
    gemm_tf32<1><<<gg, 256>>>(x, k_w, kp);
    gemm_tf32<1><<<gg, 256>>>(x, v_w, vp);

    const size_t smem = (size_t)(128 * 68 + 64 * 140 + 64 * 72 + 64 * 72 + 192) * 4;
    cudaFuncSetAttribute(attn_tf32, cudaFuncAttributeMaxDynamicSharedMemorySize, (int)smem);
    attn_tf32<<<dim3(SS / 128, BB * HH), 256, smem>>>();

    gemm_tf32<0><<<gg, 256>>>(cp, o_w, (float*)d_out);
}

// round 8
// speedup vs baseline: 4.0085x; 1.0037x over previous
#include <cuda_runtime.h>
#include <cuda_bf16.h>
#include <math.h>

// Problem constants
#define BB 2
#define SS 2048
#define DD 1024
#define HH 16
#define DK 64
#define ND (2*SS-1)          // 4095 relative-distance slots
#define MM (BB*SS)           // 4096 rows in the GEMMs

// Scratch (allocation-free: __device__ globals)
__device__ float g_q[BB*HH*SS*DK];     // [B,H,S,DK]
__device__ float g_k[BB*HH*SS*DK];
__device__ float g_v[BB*HH*SS*DK];
__device__ float g_ctx[BB*SS*HH*DK];   // [B,S,H*DK]
__device__ float g_bias[HH*ND];        // [H, rel+S-1]

// ---------------------------------------------------------------------------
// TF32 helpers
// ---------------------------------------------------------------------------
__device__ __forceinline__ unsigned f2tf(float x) {
    unsigned u;
    asm("cvt.rna.tf32.f32 %0, %1;" : "=r"(u) : "f"(x));
    return u;
}

__device__ __forceinline__ void mma8(float& d0, float& d1, float& d2, float& d3,
                                     unsigned a0, unsigned a1, unsigned a2, unsigned a3,
                                     unsigned b0, unsigned b1) {
    asm volatile("mma.sync.aligned.m16n8k8.row.col.f32.tf32.tf32.f32 "
                 "{%0,%1,%2,%3},{%4,%5,%6,%7},{%8,%9},{%0,%1,%2,%3};"
                 : "+f"(d0), "+f"(d1), "+f"(d2), "+f"(d3)
                 : "r"(a0), "r"(a1), "r"(a2), "r"(a3), "r"(b0), "r"(b1));
}

// Permutation for 64-wide K-dim (attention Q/K): group cols by (c mod 4) so a
// thread's fragment words are contiguous; swizzle keeps LDS.128 conflict-free.
__device__ __forceinline__ int qperm(int c) {
    int cp = (c & 3) * 16 + (c >> 2);
    return cp ^ (((c & 3) >> 1) * 8);
}

// ---------------------------------------------------------------------------
// Bias precompute (correctness-proven)
// ---------------------------------------------------------------------------
__global__ void bias_precompute(const float* __restrict__ rel_bias) {
    int idx = blockIdx.x * blockDim.x + threadIdx.x;
    if (idx >= ND) return;
    int rel = idx - (SS - 1);        // rel = mem - ctx = j - i
    int n = -rel;
    int ret = (n < 0) ? 16 : 0;      // num_buckets//2 = 16
    n = (n < 0) ? -n : n;
    int bucket;
    if (n < 8) {
        bucket = n;
    } else {
        double v = log((double)n / 8.0) / log(16.0) * 8.0;
        int vi = 8 + (int)v;
        bucket = (vi < 15) ? vi : 15;
    }
    bucket += ret;
#pragma unroll
    for (int h = 0; h < HH; h++)
        g_bias[h * ND + idx] = rel_bias[bucket * HH + h];
}

// ---------------------------------------------------------------------------
// TF32 tensor-core GEMM (NT): C[m,n] = sum_k A[m,k] * B[n,k].
// M=4096, N=1024, K=1024. 128x128x32 tile, 256 threads (8 warps, 2x4 grid).
// K-dim permuted layout: c' = (c&3)*8 + (c>>2), phys = c' ^ 4*(r&1),
// stride 40 (mod 32 = 8): staging STS.32 AND fragment LDS.128 conflict-free.
// One LDS.128 yields fragment words for all 4 k8-steps of a 32-K chunk.
// Register prefetch of the next global tile overlaps LDG with the MMA block.
// blockIdx.z selects (B,C) pair; MODE 1 writes [B,H,S,DK], MODE 0 row-major.
// ---------------------------------------------------------------------------
template <int MODE>
__global__ __launch_bounds__(256, 1) void gemm_tf32(
        const float* __restrict__ A,
        const float* __restrict__ B0p, const float* __restrict__ B1p,
        const float* __restrict__ B2p,
        float* __restrict__ C0p, float* __restrict__ C1p, float* __restrict__ C2p) {
    __shared__ unsigned As[128][40];
    __shared__ unsigned Bs[128][40];
    const int t = threadIdx.x, lane = t & 31, g = lane >> 2, tig = lane & 3;
    const int w = t >> 5, wm = w >> 2, wn = w & 3;
    const int bm = blockIdx.y * 128, bn = blockIdx.x * 128;
    const int z = blockIdx.z;
    const float* Bm = (z == 0) ? B0p : (z == 1) ? B1p : B2p;
    float* C = (z == 0) ? C0p : (z == 1) ? C1p : C2p;

    float acc[4][4][4];
#pragma unroll
    for (int a = 0; a < 4; a++)
#pragma unroll
        for (int b = 0; b < 4; b++)
#pragma unroll
            for (int c = 0; c < 4; c++) acc[a][b][c] = 0.f;

    // staging indices: 1024 float4-chunks per matrix, 4 per thread
    int srow[4], scol[4];
#pragma unroll
    for (int i = 0; i < 4; i++) {
        int lin = t + 256 * i;
        srow[i] = lin >> 3;          // 0..127
        scol[i] = lin & 7;           // chunk index a
    }

    float4 pa[4], pb[4];
#pragma unroll
    for (int i = 0; i < 4; i++) {
        pa[i] = *(const float4*)(A  + (size_t)(bm + srow[i]) * 1024 + scol[i] * 4);
        pb[i] = *(const float4*)(Bm + (size_t)(bn + srow[i]) * 1024 + scol[i] * 4);
    }

    const int sw = (g & 1) * 4;
    const int ca0 = (tig * 8) ^ sw;       // logical words 0-3 (kk = 0, 8)
    const int ca1 = (tig * 8 + 4) ^ sw;   // logical words 4-7 (kk = 16, 24)

    for (int k0 = 0; k0 < 1024; k0 += 32) {
        __syncthreads();
        // store prefetched tile (permuted + swizzled), cvt to tf32
#pragma unroll
        for (int i = 0; i < 4; i++) {
            const int r = srow[i];
            const int ap = scol[i] ^ ((r & 1) * 4);
            As[r][ap + 0]  = f2tf(pa[i].x);
            As[r][ap + 8]  = f2tf(pa[i].y);
            As[r][ap + 16] = f2tf(pa[i].z);
            As[r][ap + 24] = f2tf(pa[i].w);
            Bs[r][ap + 0]  = f2tf(pb[i].x);
            Bs[r][ap + 8]  = f2tf(pb[i].y);
            Bs[r][ap + 16] = f2tf(pb[i].z);
            Bs[r][ap + 24] = f2tf(pb[i].w);
        }
        __syncthreads();
        if (k0 + 32 < 1024) {
#pragma unroll
            for (int i = 0; i < 4; i++) {
                pa[i] = *(const float4*)(A  + (size_t)(bm + srow[i]) * 1024 + k0 + 32 + scol[i] * 4);
                pb[i] = *(const float4*)(Bm + (size_t)(bn + srow[i]) * 1024 + k0 + 32 + scol[i] * 4);
            }
        }

        // B fragments for all 4 tn, all 4 kk-steps: 8 LDS.128
        uint4 Bf0[4], Bf1[4];
#pragma unroll
        for (int tn = 0; tn < 4; tn++) {
            const int c = wn * 32 + tn * 8 + g;    // c&1 == g&1
            Bf0[tn] = *(const uint4*)&Bs[c][ca0];
            Bf1[tn] = *(const uint4*)&Bs[c][ca1];
        }
#pragma unroll
        for (int tm = 0; tm < 4; tm++) {
            const int r = wm * 64 + tm * 16 + g;   // r&1 == g&1
            uint4 A00 = *(const uint4*)&As[r][ca0];
            uint4 A01 = *(const uint4*)&As[r][ca1];
            uint4 A10 = *(const uint4*)&As[r + 8][ca0];
            uint4 A11 = *(const uint4*)&As[r + 8][ca1];
#pragma unroll
            for (int tn = 0; tn < 4; tn++) {
                float* d = acc[tm][tn];
                mma8(d[0], d[1], d[2], d[3], A00.x, A10.x, A00.y, A10.y, Bf0[tn].x, Bf0[tn].y); // kk=0
                mma8(d[0], d[1], d[2], d[3], A00.z, A10.z, A00.w, A10.w, Bf0[tn].z, Bf0[tn].w); // kk=8
                mma8(d[0], d[1], d[2], d[3], A01.x, A11.x, A01.y, A11.y, Bf1[tn].x, Bf1[tn].y); // kk=16
                mma8(d[0], d[1], d[2], d[3], A01.z, A11.z, A01.w, A11.w, Bf1[tn].z, Bf1[tn].w); // kk=24
            }
        }
    }

#pragma unroll
    for (int tm = 0; tm < 4; tm++) {
#pragma unroll
        for (int tn = 0; tn < 4; tn++) {
            int m = bm + wm * 64 + tm * 16 + g;
            int n = bn + wn * 32 + tn * 8 + tig * 2;
            float2 v0 = make_float2(acc[tm][tn][0], acc[tm][tn][1]);
            float2 v1 = make_float2(acc[tm][tn][2], acc[tm][tn][3]);
            if (MODE == 0) {
                *(float2*)&C[(size_t)m * 1024 + n] = v0;
                *(float2*)&C[(size_t)(m + 8) * 1024 + n] = v1;
            } else {
                int h = n >> 6, dk = n & 63;
                int b0_ = m >> 11, s0 = m & 2047;
                *(float2*)&C[(((size_t)(b0_ * HH + h)) * SS + s0) * DK + dk] = v0;
                int m1 = m + 8;
                int b1_ = m1 >> 11, s1 = m1 & 2047;
                *(float2*)&C[(((size_t)(b1_ * HH + h)) * SS + s1) * DK + dk] = v1;
            }
        }
    }
}

// ---------------------------------------------------------------------------
// Flash attention with TF32 mma. CTA = 128 q-rows x (b,h); k in 64-col tiles.
// Q and K stored in qperm() layout (stride 68): Q fragments are loaded ONCE
// into registers (loop-invariant, 8 LDS.128); K fragments are 4 LDS.128 per
// tn per tile (vs 16 LDS.32). Softmax is warp-local. P roundtrips through
// per-warp-private smem (stride 140); V stays row-major stride 72.
// ---------------------------------------------------------------------------
__global__ __launch_bounds__(256, 1) void attn_tf32() {
    extern __shared__ unsigned smu[];
    unsigned* Qs = smu;                   // [128][68]  permuted (stride mod32 = 4)
    unsigned* Ps = Qs + 128 * 68;         // [64][140]
    unsigned* Ks = Ps + 64 * 140;         // [64][68]   permuted
    unsigned* Vs = Ks + 64 * 68;          // [64][72]   row-major
    float* bias_s = (float*)(Vs + 64 * 72);   // [192] (191 used)

    const int t = threadIdx.x, lane = t & 31, g = lane >> 2, tig = lane & 3;
    const int w = t >> 5;
    const int bh = blockIdx.y, h = bh & 15, b_ = bh >> 4;
    const int q0 = blockIdx.x * 128;
    const float* qg = g_q + (size_t)bh * SS * DK;
    const float* kg = g_k + (size_t)bh * SS * DK;
    const float* vg = g_v + (size_t)bh * SS * DK;

    // Stage Q [128][64] -> permuted Qs
#pragma unroll
    for (int i = 0; i < 8; i++) {
        int lin = t + 256 * i;            // 0..2047
        int r = lin >> 4, a = lin & 15;
        float4 v = *(const float4*)(qg + (size_t)(q0 + r) * DK + a * 4);
        unsigned* qr = &Qs[r * 68];
        qr[qperm(4 * a + 0)] = f2tf(v.x);
        qr[qperm(4 * a + 1)] = f2tf(v.y);
        qr[qperm(4 * a + 2)] = f2tf(v.z);
        qr[qperm(4 * a + 3)] = f2tf(v.w);
    }
    __syncthreads();

    const int rb = w * 16;
    const int r0 = rb + g, r1 = rb + g + 8;

    // Loop-invariant Q fragments: words for all 8 d-steps, rows r0 and r1
    const int fc[4] = { (tig * 16 + 0)  ^ ((tig >> 1) * 8),
                        (tig * 16 + 4)  ^ ((tig >> 1) * 8),
                        (tig * 16 + 8)  ^ ((tig >> 1) * 8),
                        (tig * 16 + 12) ^ ((tig >> 1) * 8) };
    uint4 Aq0[4], Aq1[4];
#pragma unroll
    for (int u = 0; u < 4; u++) {
        Aq0[u] = *(const uint4*)&Qs[r0 * 68 + fc[u]];
        Aq1[u] = *(const uint4*)&Qs[r1 * 68 + fc[u]];
    }

    float oacc[8][4];
#pragma unroll
    for (int tn = 0; tn < 8; tn++)
#pragma unroll
        for (int c = 0; c < 4; c++) oacc[tn][c] = 0.f;
    float m0 = -INFINITY, m1 = -INFINITY, l0 = 0.f, l1 = 0.f;

    for (int kt = 0; kt < SS / 64; kt++) {
        const int kb = kt * 64;
        __syncthreads();                  // prev Ks/Vs/Ps consumed
#pragma unroll
        for (int i = 0; i < 4; i++) {
            int lin = t + 256 * i;        // 0..1023
            int c = lin >> 4, a = lin & 15;
            float4 kv = *(const float4*)(kg + (size_t)(kb + c) * DK + a * 4);
            float4 vv = *(const float4*)(vg + (size_t)(kb + c) * DK + a * 4);
            unsigned* kr = &Ks[c * 68];
            kr[qperm(4 * a + 0)] = f2tf(kv.x);
            kr[qperm(4 * a + 1)] = f2tf(kv.y);
            kr[qperm(4 * a + 2)] = f2tf(kv.z);
            kr[qperm(4 * a + 3)] = f2tf(kv.w);
            *(uint4*)&Vs[c * 72 + a * 4] =
                make_uint4(f2tf(vv.x), f2tf(vv.y), f2tf(vv.z), f2tf(vv.w));
        }
        if (t < 191)                      // rel in [-2047, 2047] exactly; no clamp needed
            bias_s[t] = g_bias[h * ND + (kb - q0 - 127 + t) + (SS - 1)];
        __syncthreads();

        // S = Q @ K^T  (warp strip: 16 rows x 64 cols)
        float sv[8][4];
#pragma unroll
        for (int tn = 0; tn < 8; tn++)
#pragma unroll
            for (int c = 0; c < 4; c++) sv[tn][c] = 0.f;

#pragma unroll
        for (int tn = 0; tn < 8; tn++) {
            const int krow = (tn * 8 + g) * 68;
            float* d = sv[tn];
#pragma unroll
            for (int u = 0; u < 4; u++) {
                uint4 Kf = *(const uint4*)&Ks[krow + fc[u]];
                mma8(d[0], d[1], d[2], d[3],
                     Aq0[u].x, Aq1[u].x, Aq0[u].y, Aq1[u].y, Kf.x, Kf.y);  // d0 = 16u
                mma8(d[0], d[1], d[2], d[3],
                     Aq0[u].z, Aq1[u].z, Aq0[u].w, Aq1[u].w, Kf.z, Kf.w);  // d0 = 16u+8
            }
        }

        // bias + warp-local online softmax (rows r0, r1)
        float mx0 = -INFINITY, mx1 = -INFINITY;
#pragma unroll
        for (int tn = 0; tn < 8; tn++) {
            int c = tn * 8 + tig * 2;
            sv[tn][0] += bias_s[c - r0 + 127];
            sv[tn][1] += bias_s[c + 1 - r0 + 127];
            sv[tn][2] += bias_s[c - r1 + 127];
            sv[tn][3] += bias_s[c + 1 - r1 + 127];
            mx0 = fmaxf(mx0, fmaxf(sv[tn][0], sv[tn][1]));
            mx1 = fmaxf(mx1, fmaxf(sv[tn][2], sv[tn][3]));
        }
        mx0 = fmaxf(mx0, __shfl_xor_sync(0xffffffffu, mx0, 1));
        mx0 = fmaxf(mx0, __shfl_xor_sync(0xffffffffu, mx0, 2));
        mx1 = fmaxf(mx1, __shfl_xor_sync(0xffffffffu, mx1, 1));
        mx1 = fmaxf(mx1, __shfl_xor_sync(0xffffffffu, mx1, 2));
        const float mn0 = fmaxf(m0, mx0), mn1 = fmaxf(m1, mx1);
        const float sc0 = __expf(m0 - mn0), sc1 = __expf(m1 - mn1);
        float s0 = 0.f, s1 = 0.f;
#pragma unroll
        for (int tn = 0; tn < 8; tn++) {
            sv[tn][0] = __expf(sv[tn][0] - mn0);
            sv[tn][1] = __expf(sv[tn][1] - mn0);
            sv[tn][2] = __expf(sv[tn][2] - mn1);
            sv[tn][3] = __expf(sv[tn][3] - mn1);
            s0 += sv[tn][0] + sv[tn][1];
            s1 += sv[tn][2] + sv[tn][3];
        }
        s0 += __shfl_xor_sync(0xffffffffu, s0, 1);
        s0 += __shfl_xor_sync(0xffffffffu, s0, 2);
        s1 += __shfl_xor_sync(0xffffffffu, s1, 1);
        s1 += __shfl_xor_sync(0xffffffffu, s1, 2);
        l0 = l0 * sc0 + s0; l1 = l1 * sc1 + s1;
        m0 = mn0; m1 = mn1;

        // rescale O, spill P (warp-private rows -> only __syncwarp needed)
#pragma unroll
        for (int tn = 0; tn < 8; tn++) {
            oacc[tn][0] *= sc0; oacc[tn][1] *= sc0;
            oacc[tn][2] *= sc1; oacc[tn][3] *= sc1;
            int c = tn * 8 + tig * 2;
            Ps[(c)     * 140 + r0] = f2tf(sv[tn][0]);
            Ps[(c + 1) * 140 + r0] = f2tf(sv[tn][1]);
            Ps[(c)     * 140 + r1] = f2tf(sv[tn][2]);
            Ps[(c + 1) * 140 + r1] = f2tf(sv[tn][3]);
        }
        __syncwarp();

        // O += P @ V
#pragma unroll
        for (int c0 = 0; c0 < 64; c0 += 8) {
            unsigned a0 = Ps[(c0 + tig) * 140 + r0];
            unsigned a1 = Ps[(c0 + tig) * 140 + r1];
            unsigned a2 = Ps[(c0 + tig + 4) * 140 + r0];
            unsigned a3 = Ps[(c0 + tig + 4) * 140 + r1];
#pragma unroll
            for (int tn = 0; tn < 8; tn++) {
                unsigned bf0 = Vs[(c0 + tig) * 72 + tn * 8 + g];
                unsigned bf1 = Vs[(c0 + tig + 4) * 72 + tn * 8 + g];
                mma8(oacc[tn][0], oacc[tn][1], oacc[tn][2], oacc[tn][3],
                     a0, a1, a2, a3, bf0, bf1);
            }
        }
    }

    // Normalize + write ctx in [B, S, H*DK]
    const float i0 = 1.f / l0, i1 = 1.f / l1;
    float* op = g_ctx + ((size_t)b_ * SS + q0) * DD + h * DK;
#pragma unroll
    for (int tn = 0; tn < 8; tn++) {
        int n = tn * 8 + tig * 2;
        *(float2*)&op[(size_t)(rb + g) * DD + n] =
            make_float2(oacc[tn][0] * i0, oacc[tn][1] * i0);
        *(float2*)&op[(size_t)(rb + g + 8) * DD + n] =
            make_float2(oacc[tn][2] * i1, oacc[tn][3] * i1);
    }
}

// ---------------------------------------------------------------------------
extern "C" void kernel_launch(void* const* d_in, const int* in_sizes, int n_in,
                              void* d_out, int out_size) {
    const float* x        = (const float*)d_in[0];
    const float* q_w      = (const float*)d_in[1];
    const float* k_w      = (const float*)d_in[2];
    const float* v_w      = (const float*)d_in[3];
    const float* o_w      = (const float*)d_in[4];
    const float* rel_bias = (const float*)d_in[5];

    float *qp, *kp, *vp, *cp;
    cudaGetSymbolAddress((void**)&qp, g_q);
    cudaGetSymbolAddress((void**)&kp, g_k);
    cudaGetSymbolAddress((void**)&vp, g_v);
    cudaGetSymbolAddress((void**)&cp, g_ctx);

    bias_precompute<<<(ND + 255) / 256, 256>>>(rel_bias);

    // Fused QKV projection: grid.z picks the weight/output pair
    gemm_tf32<1><<<dim3(8, 32, 3), 256>>>(x, q_w, k_w, v_w, qp, kp, vp);

    const size_t smem = (size_t)(128 * 68 + 64 * 140 + 64 * 68 + 64 * 72 + 192) * 4;
    cudaFuncSetAttribute(attn_tf32, cudaFuncAttributeMaxDynamicSharedMemorySize, (int)smem);
    attn_tf32<<<dim3(SS / 128, BB * HH), 256, smem>>>();

    // Output projection
    gemm_tf32<0><<<dim3(8, 32, 1), 256>>>(cp, o_w, o_w, o_w,
                                          (float*)d_out, (float*)d_out, (float*)d_out);
}

// round 10
// speedup vs baseline: 4.2860x; 1.0692x over previous
#include <cuda_runtime.h>
#include <cuda_bf16.h>
#include <math.h>

// Problem constants
#define BB 2
#define SS 2048
#define DD 1024
#define HH 16
#define DK 64
#define ND (2*SS-1)          // 4095 relative-distance slots
#define MM (BB*SS)           // 4096 rows in the GEMMs

// Scratch (allocation-free: __device__ globals)
__device__ float g_q[BB*HH*SS*DK];     // [B,H,S,DK]
__device__ float g_k[BB*HH*SS*DK];
__device__ float g_v[BB*HH*SS*DK];
__device__ float g_ctx[BB*SS*HH*DK];   // [B,S,H*DK]
__device__ float g_bias[HH*ND];        // [H, rel+S-1]

// ---------------------------------------------------------------------------
// TF32 helpers
// ---------------------------------------------------------------------------
__device__ __forceinline__ unsigned f2tf(float x) {
    unsigned u;
    asm("cvt.rna.tf32.f32 %0, %1;" : "=r"(u) : "f"(x));
    return u;
}

__device__ __forceinline__ void mma8(float& d0, float& d1, float& d2, float& d3,
                                     unsigned a0, unsigned a1, unsigned a2, unsigned a3,
                                     unsigned b0, unsigned b1) {
    asm volatile("mma.sync.aligned.m16n8k8.row.col.f32.tf32.tf32.f32 "
                 "{%0,%1,%2,%3},{%4,%5,%6,%7},{%8,%9},{%0,%1,%2,%3};"
                 : "+f"(d0), "+f"(d1), "+f"(d2), "+f"(d3)
                 : "r"(a0), "r"(a1), "r"(a2), "r"(a3), "r"(b0), "r"(b1));
}

// Permutation for 64-wide K-dim (attention Q/K): group cols by (c mod 4) so a
// thread's fragment words are contiguous; swizzle keeps LDS.128 conflict-free.
__device__ __forceinline__ int qperm(int c) {
    int cp = (c & 3) * 16 + (c >> 2);
    return cp ^ (((c & 3) >> 1) * 8);
}

// ---------------------------------------------------------------------------
// Bias precompute (correctness-proven)
// ---------------------------------------------------------------------------
__global__ void bias_precompute(const float* __restrict__ rel_bias) {
    int idx = blockIdx.x * blockDim.x + threadIdx.x;
    if (idx >= ND) return;
    int rel = idx - (SS - 1);        // rel = mem - ctx = j - i
    int n = -rel;
    int ret = (n < 0) ? 16 : 0;      // num_buckets//2 = 16
    n = (n < 0) ? -n : n;
    int bucket;
    if (n < 8) {
        bucket = n;
    } else {
        double v = log((double)n / 8.0) / log(16.0) * 8.0;
        int vi = 8 + (int)v;
        bucket = (vi < 15) ? vi : 15;
    }
    bucket += ret;
#pragma unroll
    for (int h = 0; h < HH; h++)
        g_bias[h * ND + idx] = rel_bias[bucket * HH + h];
}

// ---------------------------------------------------------------------------
// TF32 tensor-core GEMM (NT): C[m,n] = sum_k A[m,k] * B[n,k].
// 128x128x32 tile, 256 threads (8 warps, 2x4). Frag-vectorized permuted smem
// (stride 40, swizzle ^4*(r&1)): staging STS.32 and fragment LDS.128 both
// conflict-free. Staging covers ALL 1024 float4-chunks per matrix (4 per
// thread), loads batched (MLP=8) before stores. No persistent prefetch:
// regs <=128 so TWO CTAs co-reside (launch_bounds(256,2)).
// blockIdx.z selects (B,C) pair; MODE 1 writes [B,H,S,DK], MODE 0 row-major.
// ---------------------------------------------------------------------------
template <int MODE>
__global__ __launch_bounds__(256, 2) void gemm_tf32(
        const float* __restrict__ A,
        const float* __restrict__ B0p, const float* __restrict__ B1p,
        const float* __restrict__ B2p,
        float* __restrict__ C0p, float* __restrict__ C1p, float* __restrict__ C2p) {
    __shared__ unsigned As[128][40];
    __shared__ unsigned Bs[128][40];
    const int t = threadIdx.x, lane = t & 31, g = lane >> 2, tig = lane & 3;
    const int w = t >> 5, wm = w >> 2, wn = w & 3;
    const int bm = blockIdx.y * 128, bn = blockIdx.x * 128;
    const int z = blockIdx.z;
    const float* Bm = (z == 0) ? B0p : (z == 1) ? B1p : B2p;
    float* C = (z == 0) ? C0p : (z == 1) ? C1p : C2p;

    float acc[4][4][4];
#pragma unroll
    for (int a = 0; a < 4; a++)
#pragma unroll
        for (int b = 0; b < 4; b++)
#pragma unroll
            for (int c = 0; c < 4; c++) acc[a][b][c] = 0.f;

    // staging indices: 1024 float4-chunks per matrix, 4 per thread
    int srow[4], scol[4];
#pragma unroll
    for (int i = 0; i < 4; i++) {
        int lin = t + 256 * i;
        srow[i] = lin >> 3;          // 0..127
        scol[i] = lin & 7;           // chunk index 0..7
    }

    const int sw = (g & 1) * 4;
    const int ca0 = (tig * 8) ^ sw;       // logical words 0-3 (kk = 0, 8)
    const int ca1 = (tig * 8 + 4) ^ sw;   // logical words 4-7 (kk = 16, 24)

    for (int k0 = 0; k0 < 1024; k0 += 32) {
        // batch all 8 global loads first (MLP=8), then convert+store
        float4 av[4], bv[4];
#pragma unroll
        for (int i = 0; i < 4; i++) {
            av[i] = *(const float4*)(A  + (size_t)(bm + srow[i]) * 1024 + k0 + scol[i] * 4);
            bv[i] = *(const float4*)(Bm + (size_t)(bn + srow[i]) * 1024 + k0 + scol[i] * 4);
        }
        __syncthreads();
#pragma unroll
        for (int i = 0; i < 4; i++) {
            const int r = srow[i];
            const int ap = scol[i] ^ ((r & 1) * 4);
            As[r][ap + 0]  = f2tf(av[i].x);
            As[r][ap + 8]  = f2tf(av[i].y);
            As[r][ap + 16] = f2tf(av[i].z);
            As[r][ap + 24] = f2tf(av[i].w);
            Bs[r][ap + 0]  = f2tf(bv[i].x);
            Bs[r][ap + 8]  = f2tf(bv[i].y);
            Bs[r][ap + 16] = f2tf(bv[i].z);
            Bs[r][ap + 24] = f2tf(bv[i].w);
        }
        __syncthreads();

        // B fragments for all 4 tn, all 4 kk-steps: 8 LDS.128
        uint4 Bf0[4], Bf1[4];
#pragma unroll
        for (int tn = 0; tn < 4; tn++) {
            const int c = wn * 32 + tn * 8 + g;    // c&1 == g&1
            Bf0[tn] = *(const uint4*)&Bs[c][ca0];
            Bf1[tn] = *(const uint4*)&Bs[c][ca1];
        }
#pragma unroll
        for (int tm = 0; tm < 4; tm++) {
            const int r = wm * 64 + tm * 16 + g;   // r&1 == g&1
            uint4 A00 = *(const uint4*)&As[r][ca0];
            uint4 A01 = *(const uint4*)&As[r][ca1];
            uint4 A10 = *(const uint4*)&As[r + 8][ca0];
            uint4 A11 = *(const uint4*)&As[r + 8][ca1];
#pragma unroll
            for (int tn = 0; tn < 4; tn++) {
                float* d = acc[tm][tn];
                mma8(d[0], d[1], d[2], d[3], A00.x, A10.x, A00.y, A10.y, Bf0[tn].x, Bf0[tn].y); // kk=0
                mma8(d[0], d[1], d[2], d[3], A00.z, A10.z, A00.w, A10.w, Bf0[tn].z, Bf0[tn].w); // kk=8
                mma8(d[0], d[1], d[2], d[3], A01.x, A11.x, A01.y, A11.y, Bf1[tn].x, Bf1[tn].y); // kk=16
                mma8(d[0], d[1], d[2], d[3], A01.z, A11.z, A01.w, A11.w, Bf1[tn].z, Bf1[tn].w); // kk=24
            }
        }
    }

#pragma unroll
    for (int tm = 0; tm < 4; tm++) {
#pragma unroll
        for (int tn = 0; tn < 4; tn++) {
            int m = bm + wm * 64 + tm * 16 + g;
            int n = bn + wn * 32 + tn * 8 + tig * 2;
            float2 v0 = make_float2(acc[tm][tn][0], acc[tm][tn][1]);
            float2 v1 = make_float2(acc[tm][tn][2], acc[tm][tn][3]);
            if (MODE == 0) {
                *(float2*)&C[(size_t)m * 1024 + n] = v0;
                *(float2*)&C[(size_t)(m + 8) * 1024 + n] = v1;
            } else {
                int h = n >> 6, dk = n & 63;
                int b0_ = m >> 11, s0 = m & 2047;
                *(float2*)&C[(((size_t)(b0_ * HH + h)) * SS + s0) * DK + dk] = v0;
                int m1 = m + 8;
                int b1_ = m1 >> 11, s1 = m1 & 2047;
                *(float2*)&C[(((size_t)(b1_ * HH + h)) * SS + s1) * DK + dk] = v1;
            }
        }
    }
}

// ---------------------------------------------------------------------------
// Flash attention with TF32 mma. CTA = 128 q-rows x (b,h); k in 64-col tiles.
// Q/K in qperm layout (stride 68). Q fragments are reloaded from the
// persistent Qs each k-tile (8 LDS.128) instead of living in registers —
// keeps regs <=128 so TWO CTAs co-reside (smem 2x107KB = 214KB <= 227KB);
// one CTA's MUFU-heavy softmax overlaps the other's MMA phases.
// ---------------------------------------------------------------------------
__global__ __launch_bounds__(256, 2) void attn_tf32() {
    extern __shared__ unsigned smu[];
    unsigned* Qs = smu;                   // [128][68]  permuted (stride mod32 = 4)
    unsigned* Ps = Qs + 128 * 68;         // [64][140]
    unsigned* Ks = Ps + 64 * 140;         // [64][68]   permuted
    unsigned* Vs = Ks + 64 * 68;          // [64][72]   row-major
    float* bias_s = (float*)(Vs + 64 * 72);   // [192] (191 used)

    const int t = threadIdx.x, lane = t & 31, g = lane >> 2, tig = lane & 3;
    const int w = t >> 5;
    const int bh = blockIdx.y, h = bh & 15, b_ = bh >> 4;
    const int q0 = blockIdx.x * 128;
    const float* qg = g_q + (size_t)bh * SS * DK;
    const float* kg = g_k + (size_t)bh * SS * DK;
    const float* vg = g_v + (size_t)bh * SS * DK;

    // Stage Q [128][64] -> permuted Qs (persists the whole kernel)
#pragma unroll
    for (int i = 0; i < 8; i++) {
        int lin = t + 256 * i;            // 0..2047
        int r = lin >> 4, a = lin & 15;
        float4 v = *(const float4*)(qg + (size_t)(q0 + r) * DK + a * 4);
        unsigned* qr = &Qs[r * 68];
        qr[qperm(4 * a + 0)] = f2tf(v.x);
        qr[qperm(4 * a + 1)] = f2tf(v.y);
        qr[qperm(4 * a + 2)] = f2tf(v.z);
        qr[qperm(4 * a + 3)] = f2tf(v.w);
    }

    const int rb = w * 16;
    const int r0 = rb + g, r1 = rb + g + 8;

    const int fc[4] = { (tig * 16 + 0)  ^ ((tig >> 1) * 8),
                        (tig * 16 + 4)  ^ ((tig >> 1) * 8),
                        (tig * 16 + 8)  ^ ((tig >> 1) * 8),
                        (tig * 16 + 12) ^ ((tig >> 1) * 8) };

    float oacc[8][4];
#pragma unroll
    for (int tn = 0; tn < 8; tn++)
#pragma unroll
        for (int c = 0; c < 4; c++) oacc[tn][c] = 0.f;
    float m0 = -INFINITY, m1 = -INFINITY, l0 = 0.f, l1 = 0.f;

    for (int kt = 0; kt < SS / 64; kt++) {
        const int kb = kt * 64;
        __syncthreads();                  // prev Ks/Vs/Ps consumed (also orders Qs @kt=0)
#pragma unroll
        for (int i = 0; i < 4; i++) {
            int lin = t + 256 * i;        // 0..1023
            int c = lin >> 4, a = lin & 15;
            float4 kv = *(const float4*)(kg + (size_t)(kb + c) * DK + a * 4);
            float4 vv = *(const float4*)(vg + (size_t)(kb + c) * DK + a * 4);
            unsigned* kr = &Ks[c * 68];
            kr[qperm(4 * a + 0)] = f2tf(kv.x);
            kr[qperm(4 * a + 1)] = f2tf(kv.y);
            kr[qperm(4 * a + 2)] = f2tf(kv.z);
            kr[qperm(4 * a + 3)] = f2tf(kv.w);
            *(uint4*)&Vs[c * 72 + a * 4] =
                make_uint4(f2tf(vv.x), f2tf(vv.y), f2tf(vv.z), f2tf(vv.w));
        }
        if (t < 191)                      // rel in [-2047, 2047] exactly; no clamp needed
            bias_s[t] = g_bias[h * ND + (kb - q0 - 127 + t) + (SS - 1)];
        __syncthreads();

        // Q fragments for this tile (cheap: 8 LDS.128, conflict-free)
        uint4 Aq0[4], Aq1[4];
#pragma unroll
        for (int u = 0; u < 4; u++) {
            Aq0[u] = *(const uint4*)&Qs[r0 * 68 + fc[u]];
            Aq1[u] = *(const uint4*)&Qs[r1 * 68 + fc[u]];
        }

        // S = Q @ K^T  (warp strip: 16 rows x 64 cols)
        float sv[8][4];
#pragma unroll
        for (int tn = 0; tn < 8; tn++)
#pragma unroll
            for (int c = 0; c < 4; c++) sv[tn][c] = 0.f;

#pragma unroll
        for (int tn = 0; tn < 8; tn++) {
            const int krow = (tn * 8 + g) * 68;
            float* d = sv[tn];
#pragma unroll
            for (int u = 0; u < 4; u++) {
                uint4 Kf = *(const uint4*)&Ks[krow + fc[u]];
                mma8(d[0], d[1], d[2], d[3],
                     Aq0[u].x, Aq1[u].x, Aq0[u].y, Aq1[u].y, Kf.x, Kf.y);  // d0 = 16u
                mma8(d[0], d[1], d[2], d[3],
                     Aq0[u].z, Aq1[u].z, Aq0[u].w, Aq1[u].w, Kf.z, Kf.w);  // d0 = 16u+8
            }
        }

        // bias + warp-local online softmax (rows r0, r1)
        float mx0 = -INFINITY, mx1 = -INFINITY;
#pragma unroll
        for (int tn = 0; tn < 8; tn++) {
            int c = tn * 8 + tig * 2;
            sv[tn][0] += bias_s[c - r0 + 127];
            sv[tn][1] += bias_s[c + 1 - r0 + 127];
            sv[tn][2] += bias_s[c - r1 + 127];
            sv[tn][3] += bias_s[c + 1 - r1 + 127];
            mx0 = fmaxf(mx0, fmaxf(sv[tn][0], sv[tn][1]));
            mx1 = fmaxf(mx1, fmaxf(sv[tn][2], sv[tn][3]));
        }
        mx0 = fmaxf(mx0, __shfl_xor_sync(0xffffffffu, mx0, 1));
        mx0 = fmaxf(mx0, __shfl_xor_sync(0xffffffffu, mx0, 2));
        mx1 = fmaxf(mx1, __shfl_xor_sync(0xffffffffu, mx1, 1));
        mx1 = fmaxf(mx1, __shfl_xor_sync(0xffffffffu, mx1, 2));
        const float mn0 = fmaxf(m0, mx0), mn1 = fmaxf(m1, mx1);
        const float sc0 = __expf(m0 - mn0), sc1 = __expf(m1 - mn1);
        float s0 = 0.f, s1 = 0.f;
#pragma unroll
        for (int tn = 0; tn < 8; tn++) {
            sv[tn][0] = __expf(sv[tn][0] - mn0);
            sv[tn][1] = __expf(sv[tn][1] - mn0);
            sv[tn][2] = __expf(sv[tn][2] - mn1);
            sv[tn][3] = __expf(sv[tn][3] - mn1);
            s0 += sv[tn][0] + sv[tn][1];
            s1 += sv[tn][2] + sv[tn][3];
        }
        s0 += __shfl_xor_sync(0xffffffffu, s0, 1);
        s0 += __shfl_xor_sync(0xffffffffu, s0, 2);
        s1 += __shfl_xor_sync(0xffffffffu, s1, 1);
        s1 += __shfl_xor_sync(0xffffffffu, s1, 2);
        l0 = l0 * sc0 + s0; l1 = l1 * sc1 + s1;
        m0 = mn0; m1 = mn1;

        // rescale O, spill P (warp-private rows -> only __syncwarp needed)
#pragma unroll
        for (int tn = 0; tn < 8; tn++) {
            oacc[tn][0] *= sc0; oacc[tn][1] *= sc0;
            oacc[tn][2] *= sc1; oacc[tn][3] *= sc1;
            int c = tn * 8 + tig * 2;
            Ps[(c)     * 140 + r0] = f2tf(sv[tn][0]);
            Ps[(c + 1) * 140 + r0] = f2tf(sv[tn][1]);
            Ps[(c)     * 140 + r1] = f2tf(sv[tn][2]);
            Ps[(c + 1) * 140 + r1] = f2tf(sv[tn][3]);
        }
        __syncwarp();

        // O += P @ V
#pragma unroll
        for (int c0 = 0; c0 < 64; c0 += 8) {
            unsigned a0 = Ps[(c0 + tig) * 140 + r0];
            unsigned a1 = Ps[(c0 + tig) * 140 + r1];
            unsigned a2 = Ps[(c0 + tig + 4) * 140 + r0];
            unsigned a3 = Ps[(c0 + tig + 4) * 140 + r1];
#pragma unroll
            for (int tn = 0; tn < 8; tn++) {
                unsigned bf0 = Vs[(c0 + tig) * 72 + tn * 8 + g];
                unsigned bf1 = Vs[(c0 + tig + 4) * 72 + tn * 8 + g];
                mma8(oacc[tn][0], oacc[tn][1], oacc[tn][2], oacc[tn][3],
                     a0, a1, a2, a3, bf0, bf1);
            }
        }
    }

    // Normalize + write ctx in [B, S, H*DK]
    const float i0 = 1.f / l0, i1 = 1.f / l1;
    float* op = g_ctx + ((size_t)b_ * SS + q0) * DD + h * DK;
#pragma unroll
    for (int tn = 0; tn < 8; tn++) {
        int n = tn * 8 + tig * 2;
        *(float2*)&op[(size_t)(rb + g) * DD + n] =
            make_float2(oacc[tn][0] * i0, oacc[tn][1] * i0);
        *(float2*)&op[(size_t)(rb + g + 8) * DD + n] =
            make_float2(oacc[tn][2] * i1, oacc[tn][3] * i1);
    }
}

// ---------------------------------------------------------------------------
extern "C" void kernel_launch(void* const* d_in, const int* in_sizes, int n_in,
                              void* d_out, int out_size) {
    const float* x        = (const float*)d_in[0];
    const float* q_w      = (const float*)d_in[1];
    const float* k_w      = (const float*)d_in[2];
    const float* v_w      = (const float*)d_in[3];
    const float* o_w      = (const float*)d_in[4];
    const float* rel_bias = (const float*)d_in[5];

    float *qp, *kp, *vp, *cp;
    cudaGetSymbolAddress((void**)&qp, g_q);
    cudaGetSymbolAddress((void**)&kp, g_k);
    cudaGetSymbolAddress((void**)&vp, g_v);
    cudaGetSymbolAddress((void**)&cp, g_ctx);

    bias_precompute<<<(ND + 255) / 256, 256>>>(rel_bias);

    // Fused QKV projection: grid.z picks the weight/output pair
    gemm_tf32<1><<<dim3(8, 32, 3), 256>>>(x, q_w, k_w, v_w, qp, kp, vp);

    const size_t smem = (size_t)(128 * 68 + 64 * 140 + 64 * 68 + 64 * 72 + 192) * 4;
    cudaFuncSetAttribute(attn_tf32, cudaFuncAttributeMaxDynamicSharedMemorySize, (int)smem);
    attn_tf32<<<dim3(SS / 128, BB * HH), 256, smem>>>();

    // Output projection
    gemm_tf32<0><<<dim3(8, 32, 1), 256>>>(cp, o_w, o_w, o_w,
                                          (float*)d_out, (float*)d_out, (float*)d_out);
}